// round 9
// baseline (speedup 1.0000x reference)
#include <cuda_runtime.h>

// SphericalHarmonics l<=3 (e3nn, 'integral' norm), input normalized to unit sphere.
// R6 post-mortem: smem-staged transpose costs 32 extra L1 wavefronts/warp-tile
// (output crosses the L1 crossbar 3x: STS+LDS+STG). This version: 4 lanes per
// edge, each lane computes all 16 components redundantly (~43 FMA, cheap) and
// stores exactly ONE float4 = quarter (lane&3). Output float4 index == global
// thread id -> stores perfectly dense, no smem, no barriers, no transpose.
// Input: 4-lane broadcast scalar loads (96 B span/warp = 1-2 wavefronts each).

// K = 1/sqrt(4pi) folded into coefficients
#define C_K      0.2820947917738781f   // K
#define C_KS3    0.4886025119029199f   // K*sqrt(3)
#define C_KS5    0.6307831305050401f   // K*sqrt(5)
#define C_KS15   1.0925484305920792f   // K*sqrt(15)
#define C_KS15H  0.5462742152960396f   // K*sqrt(15)/2
#define C_KS5H   0.31539156525252005f  // K*sqrt(5)/2
#define C_S7     2.6457513110645907f   // sqrt(7)      (on K-scaled sh2)
#define C_S42_6  1.0801234497346435f   // sqrt(42)/6   (on K-scaled sh2)
#define C_KS168  0.4570457994644658f   // K*sqrt(168)/8
#define C_KS7H   0.3731763325901154f   // K*sqrt(7)/2

#define NT 256

__global__ __launch_bounds__(NT) void sh_l3_kernel(
    const float* __restrict__ x, float4* __restrict__ outv, int n)
{
    const int gtid = blockIdx.x * NT + threadIdx.x;
    const int e = gtid >> 2;          // edge index (4 lanes share one edge)
    if (e >= n) return;
    const int q = gtid & 3;           // which float4 quarter this lane stores

    // 4-lane broadcast loads; warp spans 96 B per LDG -> 1-2 wavefronts
    float vx = __ldg(x + 3 * e + 0);
    float vy = __ldg(x + 3 * e + 1);
    float vz = __ldg(x + 3 * e + 2);

    float rinv = rsqrtf(vx * vx + vy * vy + vz * vz);
    vx *= rinv; vy *= rinv; vz *= rinv;

    float x2 = vx * vx;
    float y2 = vy * vy;
    float z2 = vz * vz;
    float x2z2 = x2 + z2;
    float p4y = 4.0f * y2 - x2z2;

    // l=1 (K folded)
    float o10 = C_KS3 * vx;
    float o11 = C_KS3 * vy;
    float o12 = C_KS3 * vz;
    // l=2 (K folded)
    float o20 = C_KS15 * vx * vz;
    float o21 = C_KS15 * vx * vy;
    float o22 = C_KS5 * y2 - C_KS5H * x2z2;
    float o23 = C_KS15 * vy * vz;
    float o24 = C_KS15H * (z2 - x2);
    // l=3 (recurrence on K-scaled l=2 -> already K-scaled)
    float o30 = C_S42_6 * (o20 * vz + o24 * vx);
    float o31 = C_S7 * o20 * vy;
    float o32 = C_KS168 * p4y * vx;
    float o33 = C_KS7H * vy * (2.0f * y2 - 3.0f * x2z2);
    float o34 = C_KS168 * vz * p4y;
    float o35 = C_S7 * o24 * vy;
    float o36 = C_S42_6 * (o24 * vz - o20 * vx);

    // Select this lane's quarter (SEL chain on ALU pipe, no divergence)
    float4 r;
    if (q == 0)      r = make_float4(C_K, o10, o11, o12);
    else if (q == 1) r = make_float4(o20, o21, o22, o23);
    else if (q == 2) r = make_float4(o24, o30, o31, o32);
    else             r = make_float4(o33, o34, o35, o36);

    // Dense by construction: float4 index e*4+q == gtid.
    outv[gtid] = r;
}

extern "C" void kernel_launch(void* const* d_in, const int* in_sizes, int n_in,
                              void* d_out, int out_size) {
    const float* x = (const float*)d_in[0];
    float4* outv = (float4*)d_out;
    int n = in_sizes[0] / 3;          // x is [N, 3] float32
    long long threads_total = 4LL * n;
    int blocks = (int)((threads_total + NT - 1) / NT);
    sh_l3_kernel<<<blocks, NT>>>(x, outv, n);
}

// round 10
// speedup vs baseline: 1.4013x; 1.4013x over previous
#include <cuda_runtime.h>
#include <cuda.h>
#include <cstdint>

// SphericalHarmonics l<=3 (e3nn, 'integral' norm), unit-sphere normalized input.
// R9 post-mortem: 4x redundant compute made the kernel issue-bound (55%).
// R10: R6-style compute (1 thread/edge, ~43 FMA), output staged once into a
// SW128-swizzled smem tile, then ONE TMA 2D bulk store per block. The TMA
// engine de-swizzles and writes 16 KB to GMEM: no LDS, no STG, no per-lane
// store wavefronts through L1, minimal SM issue. Output viewed as 2D
// [N/2 rows, 32 f32] with box [32,128].

#define NT 256
#define NWARP (NT / 32)
#define TILE_BYTES (NT * 64)        // 16 KB output tile per block
#define DYN_SMEM (TILE_BYTES + 1024)

// K = 1/sqrt(4pi) folded into coefficients
#define C_K      0.2820947917738781f
#define C_KS3    0.4886025119029199f   // K*sqrt(3)
#define C_KS5    0.6307831305050401f   // K*sqrt(5)
#define C_KS15   1.0925484305920792f   // K*sqrt(15)
#define C_KS15H  0.5462742152960396f   // K*sqrt(15)/2
#define C_KS5H   0.31539156525252005f  // K*sqrt(5)/2
#define C_S7     2.6457513110645907f   // sqrt(7)      (on K-scaled sh2)
#define C_S42_6  1.0801234497346435f   // sqrt(42)/6   (on K-scaled sh2)
#define C_KS168  0.4570457994644658f   // K*sqrt(168)/8
#define C_KS7H   0.3731763325901154f   // K*sqrt(7)/2

struct SH16 {
    float o10,o11,o12,o20,o21,o22,o23,o24,o30,o31,o32,o33,o34,o35,o36;
};

__device__ __forceinline__ SH16 sh_compute(float vx, float vy, float vz) {
    float rinv = rsqrtf(vx * vx + vy * vy + vz * vz);
    vx *= rinv; vy *= rinv; vz *= rinv;
    float x2 = vx * vx, y2 = vy * vy, z2 = vz * vz;
    float x2z2 = x2 + z2;
    float p4y = 4.0f * y2 - x2z2;
    SH16 s;
    s.o10 = C_KS3 * vx;  s.o11 = C_KS3 * vy;  s.o12 = C_KS3 * vz;
    s.o20 = C_KS15 * vx * vz;
    s.o21 = C_KS15 * vx * vy;
    s.o22 = C_KS5 * y2 - C_KS5H * x2z2;
    s.o23 = C_KS15 * vy * vz;
    s.o24 = C_KS15H * (z2 - x2);
    s.o30 = C_S42_6 * (s.o20 * vz + s.o24 * vx);
    s.o31 = C_S7 * s.o20 * vy;
    s.o32 = C_KS168 * p4y * vx;
    s.o33 = C_KS7H * vy * (2.0f * y2 - 3.0f * x2z2);
    s.o34 = C_KS168 * vz * p4y;
    s.o35 = C_S7 * s.o24 * vy;
    s.o36 = C_S42_6 * (s.o24 * vz - s.o20 * vx);
    return s;
}

__device__ __forceinline__ uint32_t smem_u32(const void* p) {
    uint32_t a;
    asm("{ .reg .u64 t; cvta.to.shared.u64 t, %1; cvt.u32.u64 %0, t; }"
        : "=r"(a) : "l"(p));
    return a;
}

__device__ __forceinline__ void sts128f(uint32_t addr, float a, float b, float c, float d) {
    asm volatile("st.shared.v4.f32 [%0], {%1, %2, %3, %4};"
                 :: "r"(addr), "f"(a), "f"(b), "f"(c), "f"(d) : "memory");
}

// ---------------- TMA-store kernel ----------------
__global__ __launch_bounds__(NT) void sh_l3_tma(
    const float* __restrict__ x, float* __restrict__ out, int n,
    const __grid_constant__ CUtensorMap tmap)
{
    extern __shared__ float dsm[];
    __shared__ float s_in[NWARP][96];

    const int tid  = threadIdx.x;
    const int lane = tid & 31;
    const int w    = tid >> 5;
    const int base = blockIdx.x * NT;
    const bool full = (base + NT) <= n;

    // 1024-aligned tile base for SW128
    const uint32_t tile = (smem_u32(dsm) + 1023u) & ~1023u;

    if (full) {
        // ---- input: per-warp dense float4 stage ----
        if (lane < 24) {
            const float4* xv = (const float4*)(x + (size_t)(base + w * 32) * 3);
            ((float4*)s_in[w])[lane] = xv[lane];
        }
        __syncwarp();
        float vx = s_in[w][3 * lane + 0];
        float vy = s_in[w][3 * lane + 1];
        float vz = s_in[w][3 * lane + 2];

        SH16 s = sh_compute(vx, vy, vz);

        // ---- SW128-swizzled tile write: edge tid -> row tid/2, half tid&1 ----
        // off = row*128 + half*64 + q*16; sw = off ^ ((off>>3)&0x70).
        // Per 8-lane phase: 16B-unit = 4*half + (q ^ (row&7)) -> all distinct.
        {
            const uint32_t row = (uint32_t)tid >> 1;
            const uint32_t b0 = row * 128u + ((uint32_t)tid & 1u) * 64u;
            uint32_t o0 = b0 +  0u; o0 ^= (o0 >> 3) & 0x70u;
            uint32_t o1 = b0 + 16u; o1 ^= (o1 >> 3) & 0x70u;
            uint32_t o2 = b0 + 32u; o2 ^= (o2 >> 3) & 0x70u;
            uint32_t o3 = b0 + 48u; o3 ^= (o3 >> 3) & 0x70u;
            sts128f(tile + o0, C_K,   s.o10, s.o11, s.o12);
            sts128f(tile + o1, s.o20, s.o21, s.o22, s.o23);
            sts128f(tile + o2, s.o24, s.o30, s.o31, s.o32);
            sts128f(tile + o3, s.o33, s.o34, s.o35, s.o36);
        }
        __syncthreads();
        asm volatile("fence.proxy.async.shared::cta;" ::: "memory");
        __syncthreads();

        if (tid == 0) {
            int row0 = blockIdx.x * (NT / 2);   // 128 rows per block
            asm volatile(
                "cp.async.bulk.tensor.2d.global.shared::cta.tile.bulk_group "
                "[%0, {%1, %2}], [%3];"
                :: "l"(&tmap), "r"(0), "r"(row0), "r"(tile) : "memory");
            asm volatile("cp.async.bulk.commit_group;" ::: "memory");
            asm volatile("cp.async.bulk.wait_group 0;" ::: "memory");
        }
        __syncthreads();   // no thread exits (freeing smem) before TMA drains
    } else {
        // ---- tail: plain per-thread stores (never taken at N=4M) ----
        int i = base + tid;
        if (i < n) {
            float vx = x[3 * i + 0], vy = x[3 * i + 1], vz = x[3 * i + 2];
            SH16 s = sh_compute(vx, vy, vz);
            float4* o = (float4*)(out + (size_t)16 * i);
            o[0] = make_float4(C_K,   s.o10, s.o11, s.o12);
            o[1] = make_float4(s.o20, s.o21, s.o22, s.o23);
            o[2] = make_float4(s.o24, s.o30, s.o31, s.o32);
            o[3] = make_float4(s.o33, s.o34, s.o35, s.o36);
        }
    }
}

// ---------------- fallback (proven R6 structure) ----------------
__global__ __launch_bounds__(NT) void sh_l3_fallback(
    const float* __restrict__ x, float* __restrict__ out, int n)
{
    __shared__ float  s_in[NWARP][96];
    __shared__ float4 s_out[NWARP][128];

    const int lane = threadIdx.x & 31;
    const int w    = threadIdx.x >> 5;
    const int base = blockIdx.x * NT + w * 32;
    const bool full = (base + 32) <= n;

    if (full) {
        if (lane < 24) {
            const float4* xv = (const float4*)(x + (size_t)base * 3);
            ((float4*)s_in[w])[lane] = xv[lane];
        }
        __syncwarp();
        SH16 s = sh_compute(s_in[w][3*lane], s_in[w][3*lane+1], s_in[w][3*lane+2]);
        {
            const int swz = (lane >> 1) & 3;
            float4* so = s_out[w] + lane * 4;
            so[0 ^ swz] = make_float4(C_K,   s.o10, s.o11, s.o12);
            so[1 ^ swz] = make_float4(s.o20, s.o21, s.o22, s.o23);
            so[2 ^ swz] = make_float4(s.o24, s.o30, s.o31, s.o32);
            so[3 ^ swz] = make_float4(s.o33, s.o34, s.o35, s.o36);
        }
        __syncwarp();
        float4* ov = (float4*)(out + (size_t)base * 16);
        #pragma unroll
        for (int k = 0; k < 4; k++) {
            int f = k * 32 + lane;
            int t = f >> 2, q = f & 3;
            ov[f] = s_out[w][t * 4 + (q ^ ((t >> 1) & 3))];
        }
    } else {
        int i = base + lane;
        if (i < n) {
            SH16 s = sh_compute(x[3*i], x[3*i+1], x[3*i+2]);
            float4* o = (float4*)(out + (size_t)16 * i);
            o[0] = make_float4(C_K,   s.o10, s.o11, s.o12);
            o[1] = make_float4(s.o20, s.o21, s.o22, s.o23);
            o[2] = make_float4(s.o24, s.o30, s.o31, s.o32);
            o[3] = make_float4(s.o33, s.o34, s.o35, s.o36);
        }
    }
}

typedef CUresult (*EncodeTiledFn)(
    CUtensorMap*, CUtensorMapDataType, cuuint32_t, void*,
    const cuuint64_t*, const cuuint64_t*, const cuuint32_t*, const cuuint32_t*,
    CUtensorMapInterleave, CUtensorMapSwizzle, CUtensorMapL2promotion,
    CUtensorMapFloatOOBfill);

extern "C" void kernel_launch(void* const* d_in, const int* in_sizes, int n_in,
                              void* d_out, int out_size) {
    const float* x = (const float*)d_in[0];
    float* out = (float*)d_out;
    int n = in_sizes[0] / 3;            // x is [N, 3] float32
    int blocks = (n + NT - 1) / NT;

    // Fetch cuTensorMapEncodeTiled via runtime (no -lcuda link dependency).
    EncodeTiledFn enc = nullptr;
    cudaDriverEntryPointQueryResult qr = cudaDriverEntryPointSymbolNotFound;
    cudaError_t ge = cudaGetDriverEntryPointByVersion(
        "cuTensorMapEncodeTiled", (void**)&enc, 12000, cudaEnableDefault, &qr);
    bool ok = (ge == cudaSuccess) && (qr == cudaDriverEntryPointSuccess) && enc;

    CUtensorMap tmap;
    if (ok) {
        // Output as 2D [rows = n*16/32, 32 f32], row = 128 B, SW128, box [32,128].
        cuuint64_t dims[2]    = {32ull, (cuuint64_t)((long long)n * 16 / 32)};
        cuuint64_t strides[1] = {128ull};
        cuuint32_t box[2]     = {32u, 128u};
        cuuint32_t es[2]      = {1u, 1u};
        CUresult r = enc(&tmap, CU_TENSOR_MAP_DATA_TYPE_FLOAT32, 2, d_out,
                         dims, strides, box, es,
                         CU_TENSOR_MAP_INTERLEAVE_NONE, CU_TENSOR_MAP_SWIZZLE_128B,
                         CU_TENSOR_MAP_L2_PROMOTION_L2_128B,
                         CU_TENSOR_MAP_FLOAT_OOB_FILL_NONE);
        ok = (r == CUDA_SUCCESS);
    }

    if (ok) {
        sh_l3_tma<<<blocks, NT, DYN_SMEM>>>(x, out, n, tmap);
    } else {
        sh_l3_fallback<<<blocks, NT>>>(x, out, n);
    }
}